// round 15
// baseline (speedup 1.0000x reference)
#include <cuda_runtime.h>
#include <cstdint>

// ---------------------------------------------------------------------------
// out[b] = sum_{n,p} (Agg_b^2)[n,p] * (x_b[p] . t_n)
//        + sum_n rowsum(Agg_b)[n] * s_n  +  c1
// Precompute chain (4 kernels, unchanged from R14):
//   p1 = Wl3.wl4 ; q = Wl2.p1 + wl4 ; M = Wl1.q + wl4
//   c0 = bl1.q + bl2.p1 + bl3.wl4 + bl4
//   v_n = W2 @ M_n ; t_n = W1 @ v_n ; s_n = b1.v_n ; c1 = c0 + sum_n b2.M_n
// Main kernel: persistent-lite multi-tile blocks, cp.async double buffer.
// ---------------------------------------------------------------------------

__device__ float g_p1[256];
__device__ float g_q[256];
__device__ float g_M[256];
__device__ float g_TSC[61];   // T[56], s[4], c1

__global__ void matvec256(const float* __restrict__ W, const float* __restrict__ extv,
                          const float* __restrict__ addv, int stage)
{
    const float* v = (stage == 0) ? extv : (stage == 1 ? g_p1 : g_q);
    float* outv    = (stage == 0) ? g_p1 : (stage == 1 ? g_q  : g_M);
    int warp = threadIdx.x >> 5, lane = threadIdx.x & 31;
    int r = blockIdx.x * 8 + warp;
    const float* row = W + (size_t)r * 256;
    float a = 0.f;
    #pragma unroll
    for (int k = 0; k < 8; k++) a += row[lane + 32 * k] * v[lane + 32 * k];
    #pragma unroll
    for (int o = 16; o > 0; o >>= 1) a += __shfl_xor_sync(0xFFFFFFFFu, a, o);
    if (lane == 0) outv[r] = a + (addv ? addv[r] : 0.f);
}

__global__ __launch_bounds__(512)
void finalize(const float* __restrict__ W1, const float* __restrict__ b1,
              const float* __restrict__ W2, const float* __restrict__ b2,
              const float* __restrict__ bl1, const float* __restrict__ bl2,
              const float* __restrict__ bl3, const float* __restrict__ wl4,
              const float* __restrict__ bl4)
{
    __shared__ float sM[256];
    __shared__ float sV[512];
    __shared__ float sRed[16];
    int t = threadIdx.x;
    int wid = t >> 5, lane = t & 31;
    int n = t >> 7, k = t & 127;

    float4 w[16];
    const float4* w4 = (const float4*)(W2 + (size_t)k * 64);
    #pragma unroll
    for (int j = 0; j < 16; j++) w[j] = w4[j];

    float contrib = 0.f;
    if (t < 256) {
        sM[t] = g_M[t];
        contrib = bl1[t] * g_q[t] + bl2[t] * g_p1[t] + bl3[t] * wl4[t];
    }
    __syncthreads();
    if (t < 64)
        contrib += b2[t] * (sM[t] + sM[64 + t] + sM[128 + t] + sM[192 + t]);
    #pragma unroll
    for (int o = 16; o > 0; o >>= 1) contrib += __shfl_xor_sync(0xFFFFFFFFu, contrib, o);
    if (lane == 0) sRed[wid] = contrib;

    {
        const float4* m4 = (const float4*)(sM + n * 64);
        float a = 0.f;
        #pragma unroll
        for (int j = 0; j < 16; j++) {
            float4 mm = m4[j];
            a += w[j].x * mm.x + w[j].y * mm.y + w[j].z * mm.z + w[j].w * mm.w;
        }
        sV[t] = a;
    }
    __syncthreads();

    float4 wr[4];
    int rows[4];
    #pragma unroll
    for (int rep = 0; rep < 4; rep++) {
        int r = wid * 4 + rep;
        rows[rep] = r;
        if (r < 56)      wr[rep] = ((const float4*)(W1 + (size_t)(r % 14) * 128))[lane];
        else if (r < 60) wr[rep] = ((const float4*)b1)[lane];
        else             wr[rep] = make_float4(0.f, 0.f, 0.f, 0.f);
    }
    #pragma unroll
    for (int rep = 0; rep < 4; rep++) {
        int r = rows[rep];
        if (r < 60) {
            int nn = (r < 56) ? (r / 14) : (r - 56);
            float4 vv = ((const float4*)(sV + nn * 128))[lane];
            float a = wr[rep].x * vv.x + wr[rep].y * vv.y
                    + wr[rep].z * vv.z + wr[rep].w * vv.w;
            #pragma unroll
            for (int o = 16; o > 0; o >>= 1) a += __shfl_xor_sync(0xFFFFFFFFu, a, o);
            if (lane == 0) g_TSC[r] = a;
        } else if (r == 60 && lane == 0) {
            float c = bl4[0];
            #pragma unroll
            for (int j = 0; j < 16; j++) c += sRed[j];
            g_TSC[60] = c;
        }
    }
}

// ---- packed f32x2 helpers
__device__ __forceinline__ unsigned long long pack2(float lo, float hi) {
    unsigned long long r;
    asm("mov.b64 %0, {%1, %2};" : "=l"(r) : "f"(lo), "f"(hi));
    return r;
}
__device__ __forceinline__ void fma2(unsigned long long& d,
                                     unsigned long long a, unsigned long long b) {
    asm("fma.rn.f32x2 %0, %1, %2, %0;" : "+l"(d) : "l"(a), "l"(b));
}
__device__ __forceinline__ float unpack_sum(unsigned long long v) {
    float lo, hi;
    asm("mov.b64 {%0, %1}, %2;" : "=f"(lo), "=f"(hi) : "l"(v));
    return lo + hi;
}

// ---- main kernel: multi-tile, cp.async DOUBLE BUFFER in dynamic smem
#define TPB      128
#define XBYTES   (TPB * 15 * 16)            // 30720: 60 floats/sample (pad 56->60)
#define EBYTES   (TPB * 7 * 16)             // 14336: 28 ints/sample  (pad 24->28)
#define BUFBYTES (XBYTES + EBYTES)          // 45056
#define SMEMBYTES (2 * BUFBYTES + 256)      // 90368

__global__ __launch_bounds__(TPB)
void gcn_main(const float* __restrict__ x, const int* __restrict__ eidx,
              float* __restrict__ out, int ntile, int nblk)
{
    extern __shared__ __align__(16) char smem[];
    float* sT = (float*)(smem + 2 * BUFBYTES);
    int tid = threadIdx.x;

    int tile0 = blockIdx.x;
    if (tile0 >= ntile) return;

    // stage tile -> buffer via cp.async (zero-register transpose-scatter)
    auto stage = [&](int tile, int buf) {
        char* base = smem + buf * BUFBYTES;
        const float4* Xg = (const float4*)x + (size_t)tile * TPB * 14;
        const int4*   Eg = (const int4*)eidx + (size_t)tile * TPB * 6;
        #pragma unroll
        for (int i = 0; i < 14; i++) {
            int idx4 = i * TPB + tid;
            int s = idx4 / 14, j = idx4 % 14;
            unsigned dst = (unsigned)__cvta_generic_to_shared(base + (s * 15 + j) * 16);
            asm volatile("cp.async.cg.shared.global [%0], [%1], 16;\n"
                         :: "r"(dst), "l"(Xg + idx4) : "memory");
        }
        #pragma unroll
        for (int i = 0; i < 6; i++) {
            int i4 = i * TPB + tid;
            int s = i4 / 6, r = i4 % 6;
            unsigned dst = (unsigned)__cvta_generic_to_shared(base + XBYTES + (s * 7 + r) * 16);
            asm volatile("cp.async.cg.shared.global [%0], [%1], 16;\n"
                         :: "r"(dst), "l"(Eg + i4) : "memory");
        }
        asm volatile("cp.async.commit_group;\n" ::: "memory");
    };

    stage(tile0, 0);
    if (tid < 61) sT[tid] = g_TSC[tid];

    int buf = 0;
    for (int tile = tile0; tile < ntile; tile += nblk, buf ^= 1) {
        int next = tile + nblk;
        if (next < ntile) {
            stage(next, buf ^ 1);                             // prefetch ahead
            asm volatile("cp.async.wait_group 1;\n" ::: "memory");  // tile's group done
        } else {
            asm volatile("cp.async.wait_group 0;\n" ::: "memory");
        }
        __syncthreads();

        char* base = smem + buf * BUFBYTES;

        // ---- edges: 6 LDS.128 (stride 112B, conflict-free)
        const int4* me4 = (const int4*)(base + XBYTES) + tid * 7;
        int4 f0 = me4[0], f1 = me4[1], f2 = me4[2];
        int4 f3 = me4[3], f4 = me4[4], f5 = me4[5];
        int es[12] = {f0.x,f0.y,f0.z,f0.w, f1.x,f1.y,f1.z,f1.w, f2.x,f2.y,f2.z,f2.w};
        int ed[12] = {f3.x,f3.y,f3.z,f3.w, f4.x,f4.y,f4.z,f4.w, f5.x,f5.y,f5.z,f5.w};

        unsigned h0 = 1u + (1u << 20);         // self loops: codes 0, 5
        unsigned h1 = (1u << 8) + (1u << 28);  // codes 10, 15
        #pragma unroll
        for (int e = 0; e < 12; e++) {
            int code = (ed[e] << 2) | es[e];
            unsigned inc = 1u << ((code & 7) << 2);
            if (code & 8) h1 += inc; else h0 += inc;
        }
        float c[16];
        #pragma unroll
        for (int qd = 0; qd < 8; qd++) {
            c[qd]     = (float)((h0 >> (qd * 4)) & 15u);
            c[qd + 8] = (float)((h1 >> (qd * 4)) & 15u);
        }
        float dinv[4];
        #pragma unroll
        for (int d = 0; d < 4; d++)
            dinv[d] = rsqrtf(c[4*d] + c[4*d+1] + c[4*d+2] + c[4*d+3]);
        float A[16];
        #pragma unroll
        for (int d = 0; d < 4; d++)
            #pragma unroll
            for (int s = 0; s < 4; s++)
                A[d*4+s] = c[d*4+s] * dinv[d] * dinv[s];
        float A2[16], R[4];
        #pragma unroll
        for (int n = 0; n < 4; n++) {
            R[n] = A[n*4] + A[n*4+1] + A[n*4+2] + A[n*4+3];
            #pragma unroll
            for (int p = 0; p < 4; p++) {
                A2[n*4+p] = A[n*4+0] * A[0*4+p] + A[n*4+1] * A[1*4+p]
                          + A[n*4+2] * A[2*4+p] + A[n*4+3] * A[3*4+p];
            }
        }

        // ---- x: 14 LDS.128 (stride 240B, conflict-free)
        float4 mx4[14];
        const float4* mrow = (const float4*)base + tid * 15;
        #pragma unroll
        for (int j = 0; j < 14; j++) mx4[j] = mrow[j];

        // ---- d2[p*4+n] = x_p . t_n, packed f32x2 FMA
        unsigned long long d2[16];
        #pragma unroll
        for (int i = 0; i < 16; i++) d2[i] = 0ULL;
        #pragma unroll
        for (int q = 0; q < 7; q++) {
            unsigned long long xp[4], tp[4];
            #pragma unroll
            for (int p = 0; p < 4; p++) {
                int off = p * 14 + 2 * q;        // even -> pair within one float4
                float4 v = mx4[off >> 2];
                xp[p] = (off & 2) ? pack2(v.z, v.w) : pack2(v.x, v.y);
            }
            #pragma unroll
            for (int n = 0; n < 4; n++)
                tp[n] = *(const unsigned long long*)(sT + n * 14 + 2 * q);
            #pragma unroll
            for (int p = 0; p < 4; p++)
                #pragma unroll
                for (int n = 0; n < 4; n++)
                    fma2(d2[p*4+n], xp[p], tp[n]);
        }

        float acc = sT[60] + R[0]*sT[56] + R[1]*sT[57] + R[2]*sT[58] + R[3]*sT[59];
        #pragma unroll
        for (int n = 0; n < 4; n++)
            #pragma unroll
            for (int p = 0; p < 4; p++)
                acc += A2[n*4+p] * unpack_sum(d2[p*4+n]);

        out[tile * TPB + tid] = acc;
        __syncthreads();   // all reads of this buffer done before it is re-staged
    }
}

extern "C" void kernel_launch(void* const* d_in, const int* in_sizes, int n_in,
                              void* d_out, int out_size)
{
    const float* x   = (const float*)d_in[0];
    const int*   ei  = (const int*)  d_in[1];
    const float* W1  = (const float*)d_in[2];
    const float* b1  = (const float*)d_in[3];
    const float* W2  = (const float*)d_in[4];
    const float* b2  = (const float*)d_in[5];
    const float* Wl1 = (const float*)d_in[6];
    const float* bl1 = (const float*)d_in[7];
    const float* Wl2 = (const float*)d_in[8];
    const float* bl2 = (const float*)d_in[9];
    const float* Wl3 = (const float*)d_in[10];
    const float* bl3 = (const float*)d_in[11];
    const float* wl4 = (const float*)d_in[12];
    const float* bl4 = (const float*)d_in[13];

    int B = in_sizes[0] / 56;   // 262144
    int ntile = B / TPB;        // 2048
    int nblk = 296;             // 2 blocks/SM x 148 SMs, one wave

    cudaFuncSetAttribute(gcn_main, cudaFuncAttributeMaxDynamicSharedMemorySize,
                         SMEMBYTES);

    matvec256<<<32, 256>>>(Wl3, wl4, nullptr, 0);  // g_p1 = Wl3.wl4
    matvec256<<<32, 256>>>(Wl2, nullptr, wl4, 1);  // g_q  = Wl2.p1 + wl4
    matvec256<<<32, 256>>>(Wl1, nullptr, wl4, 2);  // g_M  = Wl1.q  + wl4
    finalize<<<1, 512>>>(W1, b1, W2, b2, bl1, bl2, bl3, wl4, bl4);
    gcn_main<<<nblk, TPB, SMEMBYTES>>>(x, ei, (float*)d_out, ntile, nblk);
}

// round 16
// speedup vs baseline: 1.0735x; 1.0735x over previous
#include <cuda_runtime.h>
#include <cstdint>

// ---------------------------------------------------------------------------
// out[b] = sum_{n,p} (Agg_b^2)[n,p] * (x_b[p] . t_n)
//        + sum_n rowsum(Agg_b)[n] * s_n  +  c1
// Precompute chain (4 kernels, unchanged from R14 = 29.0us baseline):
//   p1 = Wl3.wl4 ; q = Wl2.p1 + wl4 ; M = Wl1.q + wl4
//   c0 = bl1.q + bl2.p1 + bl3.wl4 + bl4
//   v_n = W2 @ M_n ; t_n = W1 @ v_n ; s_n = b1.v_n ; c1 = c0 + sum_n b2.M_n
// Main kernel: 444 blocks (3/SM), x double-buffered via cp.async,
// edges direct per-thread LDG.128 (contiguous 96B/sample), prefetched 1 ahead.
// ---------------------------------------------------------------------------

__device__ float g_p1[256];
__device__ float g_q[256];
__device__ float g_M[256];
__device__ float g_TSC[61];   // T[56], s[4], c1

__global__ void matvec256(const float* __restrict__ W, const float* __restrict__ extv,
                          const float* __restrict__ addv, int stage)
{
    const float* v = (stage == 0) ? extv : (stage == 1 ? g_p1 : g_q);
    float* outv    = (stage == 0) ? g_p1 : (stage == 1 ? g_q  : g_M);
    int warp = threadIdx.x >> 5, lane = threadIdx.x & 31;
    int r = blockIdx.x * 8 + warp;
    const float* row = W + (size_t)r * 256;
    float a = 0.f;
    #pragma unroll
    for (int k = 0; k < 8; k++) a += row[lane + 32 * k] * v[lane + 32 * k];
    #pragma unroll
    for (int o = 16; o > 0; o >>= 1) a += __shfl_xor_sync(0xFFFFFFFFu, a, o);
    if (lane == 0) outv[r] = a + (addv ? addv[r] : 0.f);
}

__global__ __launch_bounds__(512)
void finalize(const float* __restrict__ W1, const float* __restrict__ b1,
              const float* __restrict__ W2, const float* __restrict__ b2,
              const float* __restrict__ bl1, const float* __restrict__ bl2,
              const float* __restrict__ bl3, const float* __restrict__ wl4,
              const float* __restrict__ bl4)
{
    __shared__ float sM[256];
    __shared__ float sV[512];
    __shared__ float sRed[16];
    int t = threadIdx.x;
    int wid = t >> 5, lane = t & 31;
    int n = t >> 7, k = t & 127;

    float4 w[16];
    const float4* w4 = (const float4*)(W2 + (size_t)k * 64);
    #pragma unroll
    for (int j = 0; j < 16; j++) w[j] = w4[j];

    float contrib = 0.f;
    if (t < 256) {
        sM[t] = g_M[t];
        contrib = bl1[t] * g_q[t] + bl2[t] * g_p1[t] + bl3[t] * wl4[t];
    }
    __syncthreads();
    if (t < 64)
        contrib += b2[t] * (sM[t] + sM[64 + t] + sM[128 + t] + sM[192 + t]);
    #pragma unroll
    for (int o = 16; o > 0; o >>= 1) contrib += __shfl_xor_sync(0xFFFFFFFFu, contrib, o);
    if (lane == 0) sRed[wid] = contrib;

    {
        const float4* m4 = (const float4*)(sM + n * 64);
        float a = 0.f;
        #pragma unroll
        for (int j = 0; j < 16; j++) {
            float4 mm = m4[j];
            a += w[j].x * mm.x + w[j].y * mm.y + w[j].z * mm.z + w[j].w * mm.w;
        }
        sV[t] = a;
    }
    __syncthreads();

    float4 wr[4];
    int rows[4];
    #pragma unroll
    for (int rep = 0; rep < 4; rep++) {
        int r = wid * 4 + rep;
        rows[rep] = r;
        if (r < 56)      wr[rep] = ((const float4*)(W1 + (size_t)(r % 14) * 128))[lane];
        else if (r < 60) wr[rep] = ((const float4*)b1)[lane];
        else             wr[rep] = make_float4(0.f, 0.f, 0.f, 0.f);
    }
    #pragma unroll
    for (int rep = 0; rep < 4; rep++) {
        int r = rows[rep];
        if (r < 60) {
            int nn = (r < 56) ? (r / 14) : (r - 56);
            float4 vv = ((const float4*)(sV + nn * 128))[lane];
            float a = wr[rep].x * vv.x + wr[rep].y * vv.y
                    + wr[rep].z * vv.z + wr[rep].w * vv.w;
            #pragma unroll
            for (int o = 16; o > 0; o >>= 1) a += __shfl_xor_sync(0xFFFFFFFFu, a, o);
            if (lane == 0) g_TSC[r] = a;
        } else if (r == 60 && lane == 0) {
            float c = bl4[0];
            #pragma unroll
            for (int j = 0; j < 16; j++) c += sRed[j];
            g_TSC[60] = c;
        }
    }
}

// ---- packed f32x2 helpers
__device__ __forceinline__ unsigned long long pack2(float lo, float hi) {
    unsigned long long r;
    asm("mov.b64 %0, {%1, %2};" : "=l"(r) : "f"(lo), "f"(hi));
    return r;
}
__device__ __forceinline__ void fma2(unsigned long long& d,
                                     unsigned long long a, unsigned long long b) {
    asm("fma.rn.f32x2 %0, %1, %2, %0;" : "+l"(d) : "l"(a), "l"(b));
}
__device__ __forceinline__ float unpack_sum(unsigned long long v) {
    float lo, hi;
    asm("mov.b64 {%0, %1}, %2;" : "=f"(lo), "=f"(hi) : "l"(v));
    return lo + hi;
}

// ---- main kernel: x double-buffered in smem; edges register-prefetched
#define TPB      128
#define XBYTES   (TPB * 15 * 16)        // 30720: 60 floats/sample (pad 56->60)
#define SMEMBYTES (2 * XBYTES + 256)    // 61696

__global__ __launch_bounds__(TPB, 3)
void gcn_main(const float* __restrict__ x, const int* __restrict__ eidx,
              float* __restrict__ out, int ntile, int nblk)
{
    extern __shared__ __align__(16) char smem[];
    float* sT = (float*)(smem + 2 * XBYTES);
    int tid = threadIdx.x;

    auto stage_x = [&](int tile, int buf) {
        char* base = smem + buf * XBYTES;
        const float4* Xg = (const float4*)x + (size_t)tile * TPB * 14;
        #pragma unroll
        for (int i = 0; i < 14; i++) {
            int idx4 = i * TPB + tid;
            int s = idx4 / 14, j = idx4 % 14;
            unsigned dst = (unsigned)__cvta_generic_to_shared(base + (s * 15 + j) * 16);
            asm volatile("cp.async.cg.shared.global [%0], [%1], 16;\n"
                         :: "r"(dst), "l"(Xg + idx4) : "memory");
        }
        asm volatile("cp.async.commit_group;\n" ::: "memory");
    };

    int tile = blockIdx.x;   // grid 444 < ntile 2048: every block has >=1 tile

    // prologue: stage x(tile0), load edges(tile0) into registers
    stage_x(tile, 0);
    int4 ev[6];
    {
        const int4* Ee = (const int4*)eidx + (size_t)tile * TPB * 6 + tid * 6;
        #pragma unroll
        for (int i = 0; i < 6; i++) ev[i] = Ee[i];
    }
    if (tid < 61) sT[tid] = g_TSC[tid];

    int buf = 0;
    while (true) {
        int next = tile + nblk;
        if (next < ntile) {
            stage_x(next, buf ^ 1);                                 // prefetch ahead
            asm volatile("cp.async.wait_group 1;\n" ::: "memory");  // x(tile) landed
        } else {
            asm volatile("cp.async.wait_group 0;\n" ::: "memory");
        }
        __syncthreads();

        // ---- histogram straight from edge registers
        int es[12] = {ev[0].x,ev[0].y,ev[0].z,ev[0].w,
                      ev[1].x,ev[1].y,ev[1].z,ev[1].w,
                      ev[2].x,ev[2].y,ev[2].z,ev[2].w};
        int ed[12] = {ev[3].x,ev[3].y,ev[3].z,ev[3].w,
                      ev[4].x,ev[4].y,ev[4].z,ev[4].w,
                      ev[5].x,ev[5].y,ev[5].z,ev[5].w};
        unsigned h0 = 1u + (1u << 20);         // self loops: codes 0, 5
        unsigned h1 = (1u << 8) + (1u << 28);  // codes 10, 15
        #pragma unroll
        for (int e = 0; e < 12; e++) {
            int code = (ed[e] << 2) | es[e];
            unsigned inc = 1u << ((code & 7) << 2);
            if (code & 8) h1 += inc; else h0 += inc;
        }

        // ---- prefetch next tile's edges (latency hidden under math below)
        if (next < ntile) {
            const int4* Ee = (const int4*)eidx + (size_t)next * TPB * 6 + tid * 6;
            #pragma unroll
            for (int i = 0; i < 6; i++) ev[i] = Ee[i];
        }

        float c[16];
        #pragma unroll
        for (int qd = 0; qd < 8; qd++) {
            c[qd]     = (float)((h0 >> (qd * 4)) & 15u);
            c[qd + 8] = (float)((h1 >> (qd * 4)) & 15u);
        }
        float dinv[4];
        #pragma unroll
        for (int d = 0; d < 4; d++)
            dinv[d] = rsqrtf(c[4*d] + c[4*d+1] + c[4*d+2] + c[4*d+3]);
        float A[16];
        #pragma unroll
        for (int d = 0; d < 4; d++)
            #pragma unroll
            for (int s = 0; s < 4; s++)
                A[d*4+s] = c[d*4+s] * dinv[d] * dinv[s];
        float A2[16], R[4];
        #pragma unroll
        for (int n = 0; n < 4; n++) {
            R[n] = A[n*4] + A[n*4+1] + A[n*4+2] + A[n*4+3];
            #pragma unroll
            for (int p = 0; p < 4; p++) {
                A2[n*4+p] = A[n*4+0] * A[0*4+p] + A[n*4+1] * A[1*4+p]
                          + A[n*4+2] * A[2*4+p] + A[n*4+3] * A[3*4+p];
            }
        }

        // ---- x: 14 LDS.128 (stride 240B, conflict-free)
        float4 mx4[14];
        const float4* mrow = (const float4*)(smem + buf * XBYTES) + tid * 15;
        #pragma unroll
        for (int j = 0; j < 14; j++) mx4[j] = mrow[j];

        // ---- d2[p*4+n] = x_p . t_n, packed f32x2 FMA
        unsigned long long d2[16];
        #pragma unroll
        for (int i = 0; i < 16; i++) d2[i] = 0ULL;
        #pragma unroll
        for (int q = 0; q < 7; q++) {
            unsigned long long xp[4], tp[4];
            #pragma unroll
            for (int p = 0; p < 4; p++) {
                int off = p * 14 + 2 * q;        // even -> pair within one float4
                float4 v = mx4[off >> 2];
                xp[p] = (off & 2) ? pack2(v.z, v.w) : pack2(v.x, v.y);
            }
            #pragma unroll
            for (int n = 0; n < 4; n++)
                tp[n] = *(const unsigned long long*)(sT + n * 14 + 2 * q);
            #pragma unroll
            for (int p = 0; p < 4; p++)
                #pragma unroll
                for (int n = 0; n < 4; n++)
                    fma2(d2[p*4+n], xp[p], tp[n]);
        }

        float acc = sT[60] + R[0]*sT[56] + R[1]*sT[57] + R[2]*sT[58] + R[3]*sT[59];
        #pragma unroll
        for (int n = 0; n < 4; n++)
            #pragma unroll
            for (int p = 0; p < 4; p++)
                acc += A2[n*4+p] * unpack_sum(d2[p*4+n]);

        out[tile * TPB + tid] = acc;

        if (next >= ntile) break;
        tile = next;
        buf ^= 1;
        __syncthreads();   // reads of the buffer being re-staged are done
    }
}

extern "C" void kernel_launch(void* const* d_in, const int* in_sizes, int n_in,
                              void* d_out, int out_size)
{
    const float* x   = (const float*)d_in[0];
    const int*   ei  = (const int*)  d_in[1];
    const float* W1  = (const float*)d_in[2];
    const float* b1  = (const float*)d_in[3];
    const float* W2  = (const float*)d_in[4];
    const float* b2  = (const float*)d_in[5];
    const float* Wl1 = (const float*)d_in[6];
    const float* bl1 = (const float*)d_in[7];
    const float* Wl2 = (const float*)d_in[8];
    const float* bl2 = (const float*)d_in[9];
    const float* Wl3 = (const float*)d_in[10];
    const float* bl3 = (const float*)d_in[11];
    const float* wl4 = (const float*)d_in[12];
    const float* bl4 = (const float*)d_in[13];

    int B = in_sizes[0] / 56;   // 262144
    int ntile = B / TPB;        // 2048
    int nblk = 444;             // 3 blocks/SM x 148 SMs, one wave

    cudaFuncSetAttribute(gcn_main, cudaFuncAttributeMaxDynamicSharedMemorySize,
                         SMEMBYTES);

    matvec256<<<32, 256>>>(Wl3, wl4, nullptr, 0);  // g_p1 = Wl3.wl4
    matvec256<<<32, 256>>>(Wl2, nullptr, wl4, 1);  // g_q  = Wl2.p1 + wl4
    matvec256<<<32, 256>>>(Wl1, nullptr, wl4, 2);  // g_M  = Wl1.q  + wl4
    finalize<<<1, 512>>>(W1, b1, W2, b2, bl1, bl2, bl3, wl4, bl4);
    gcn_main<<<nblk, TPB, SMEMBYTES>>>(x, ei, (float*)d_out, ntile, nblk);
}